// round 4
// baseline (speedup 1.0000x reference)
#include <cuda_runtime.h>
#include <cuda_bf16.h>
#include <cstdint>

#define BB 8
#define TT 16
#define NN 1024
#define HH 128
#define NHEADS 8
#define SNP 4
#define NT 4096
#define EMAX 65536
#define LRELU_SLOPE 0.2f
#define MAXDEG 16
#define AP 24
#define BP 16

// ---------------- scratch (device globals) ------------------------------------
__device__ float g_x[BB*TT*NN*HH];
__device__ __nv_bfloat16 g_xh[BB*TT*NN*HH];   // k-permuted bf16 hi
__device__ __nv_bfloat16 g_xl[BB*TT*NN*HH];   // k-permuted bf16 lo
__device__ float g_feat[BB*NT*HH];
__device__ __nv_bfloat16 g_h0h[BB*NT*HH];     // layer0 out, k-permuted bf16
__device__ __nv_bfloat16 g_h0l[BB*NT*HH];
__device__ float g_h1[BB*NT*HH];
__device__ float g_el[BB*NT*NHEADS];
__device__ float g_er[BB*NT*NHEADS];
__device__ float g_last[BB*NN*HH];
__device__ __nv_bfloat16 g_lh[BB*NN*HH];      // normalized last, k-permuted bf16
__device__ __nv_bfloat16 g_ll[BB*NN*HH];
__device__ float g_stats[BB*2];
__device__ int   g_deg[NT];
__device__ int   g_cnt[NT];
__device__ int   g_off[NT+1];
__device__ int   g_eid[EMAX];
__device__ int   g_srcs[EMAX];
__device__ __nv_bfloat16 g_wth[2][HH*HH];     // W^T, k-permuted
__device__ __nv_bfloat16 g_wtl[2][HH*HH];

// ---------------- helpers ------------------------------------------------------
// k-permutation within 16-chunk: (k, k+1) and (k+8, k+9) become adjacent 4-elem groups
__device__ __forceinline__ int pos16(int k) {
    return (k & ~15) | (((k>>1)&3)<<2) | (((k>>3)&1)<<1) | (k&1);
}
__device__ __forceinline__ unsigned packbf(float x, float y) {
    __nv_bfloat162 t = __floats2bfloat162_rn(x, y);
    return *(unsigned*)&t;
}
__device__ __forceinline__ void mma16816(float* c, unsigned a0, unsigned a1,
                                         unsigned a2, unsigned a3,
                                         unsigned b0, unsigned b1) {
    asm volatile(
        "mma.sync.aligned.m16n8k16.row.col.f32.bf16.bf16.f32 "
        "{%0,%1,%2,%3},{%4,%5,%6,%7},{%8,%9},{%0,%1,%2,%3};\n"
        : "+f"(c[0]), "+f"(c[1]), "+f"(c[2]), "+f"(c[3])
        : "r"(a0), "r"(a1), "r"(a2), "r"(a3), "r"(b0), "r"(b1));
}
// fp32 fs row (residual path)
__device__ __forceinline__ const float* fs_row(int row, int iter, int left) {
    int b = row >> 12, s = (row >> 10) & 3, n = row & 1023;
    if (iter > 0 && s == 0) return &g_last[((size_t)(b*NN + n))*HH];
    int t = left + s - (iter > 0 ? 1 : 0);
    return &g_x[((size_t)((b*TT + t)*NN + n))*HH];
}

// ---------------- weight conversion + deg zero (once per call) ----------------
__global__ void k_wconv(const float* __restrict__ W0, const float* __restrict__ W1) {
    int id = blockIdx.x*blockDim.x + threadIdx.x;   // 32768
    if (id < NT) { g_deg[id] = 0; g_cnt[id] = 0; }
    int layer = id >> 14;
    int r = id & 16383;
    int k = r >> 7, n = r & 127;
    float w = (layer ? W1 : W0)[k*HH + n];
    __nv_bfloat16 hi = __float2bfloat16_rn(w);
    __nv_bfloat16 lo = __float2bfloat16_rn(w - __bfloat162float(hi));
    g_wth[layer][n*HH + pos16(k)] = hi;
    g_wtl[layer][n*HH + pos16(k)] = lo;
}

// ---------------- CSR build ---------------------------------------------------
__global__ void k_count(const int* __restrict__ edst, int E) {
    int i = blockIdx.x*blockDim.x + threadIdx.x;
    if (i < E) atomicAdd(&g_deg[edst[i]], 1);
}
__global__ void k_scan() {
    __shared__ int sh[1024];
    int tid = threadIdx.x;
    int d0 = g_deg[tid*4+0], d1 = g_deg[tid*4+1], d2 = g_deg[tid*4+2], d3 = g_deg[tid*4+3];
    int tot = d0+d1+d2+d3;
    sh[tid] = tot; __syncthreads();
    for (int o = 1; o < 1024; o <<= 1) {
        int v = (tid >= o) ? sh[tid-o] : 0;
        __syncthreads();
        sh[tid] += v;
        __syncthreads();
    }
    int excl = sh[tid] - tot;
    g_off[tid*4+0] = excl;
    g_off[tid*4+1] = excl + d0;
    g_off[tid*4+2] = excl + d0 + d1;
    g_off[tid*4+3] = excl + d0 + d1 + d2;
    if (tid == 1023) g_off[NT] = sh[1023];
}
__global__ void k_fill(const int* __restrict__ edst, int E) {
    int i = blockIdx.x*blockDim.x + threadIdx.x;
    if (i >= E) return;
    int v = edst[i];
    int slot = g_off[v] + atomicAdd(&g_cnt[v], 1);
    g_eid[slot] = i;
}
__global__ void k_sort(const int* __restrict__ esrc) {
    int v = blockIdx.x*blockDim.x + threadIdx.x;
    if (v >= NT) return;
    int o0 = g_off[v];
    int d = g_deg[v]; if (d > MAXDEG) d = MAXDEG;
    for (int i = 1; i < d; i++) {
        int key = g_eid[o0+i];
        int j = i-1;
        while (j >= 0 && g_eid[o0+j] > key) { g_eid[o0+j+1] = g_eid[o0+j]; j--; }
        g_eid[o0+j+1] = key;
    }
    for (int j = 0; j < d; j++) g_srcs[o0+j] = esrc[g_eid[o0+j]];
}

// ---------------- x precompute (pair per thread, writes fp32 + permuted bf16) --
__global__ void k_x(const float* __restrict__ in, const float* __restrict__ Win,
                    const float* __restrict__ bin, const float* __restrict__ spat,
                    const float* __restrict__ temp) {
    int idx = blockIdx.x*blockDim.x + threadIdx.x;   // B*T*N*64
    int h = (idx & 63) * 2;
    int n = (idx >> 6) & 1023;
    int t = (idx >> 16) & 15;
    int b = idx >> 20;
    size_t ib = ((size_t)(b*TT + t)*NN + n)*2;
    float i0 = in[ib], i1 = in[ib+1];
    float tv = temp[n*16+t];
    float v0 = i0*Win[h]   + i1*Win[128+h]   + bin[h]   + spat[n*128+h]   + tv;
    float v1 = i0*Win[h+1] + i1*Win[128+h+1] + bin[h+1] + spat[n*128+h+1] + tv;
    size_t row = ((size_t)(b*TT + t)*NN + n)*HH;
    *(float2*)&g_x[row + h] = make_float2(v0, v1);
    __nv_bfloat16 h0 = __float2bfloat16_rn(v0);
    __nv_bfloat16 h1 = __float2bfloat16_rn(v1);
    int p = pos16(h);
    *(unsigned*)&g_xh[row + p] = packbf(v0, v1);   // exact: bf16 round of v0,v1
    *(unsigned*)&g_xl[row + p] = packbf(v0 - __bfloat162float(h0),
                                        v1 - __bfloat162float(h1));
}

// ---------------- MMA GEMM (bf16 split, double-buffered, fused el/er) ---------
__global__ __launch_bounds__(256, 2) void k_gemm(int layer, int iter, int left,
                                                 const float* __restrict__ al,
                                                 const float* __restrict__ ar) {
    __shared__ __nv_bfloat16 sA[2][2][128*AP];   // [buf][hi/lo][row*AP + permk]
    __shared__ __nv_bfloat16 sB[2][2][128*BP];
    __shared__ float s_al[128], s_ar[128];
    int tid = threadIdx.x;
    int lane = tid & 31, warp = tid >> 5;
    int block_row = blockIdx.x * 128;

    if (layer == 0 && blockIdx.x == 0 && tid < 2*BB) g_stats[tid] = 0.f;
    if (tid < 128) { s_al[tid] = al[tid]; s_ar[tid] = ar[tid]; }

    // staging source pointers: thread stages 8 elems of row (tid>>1), half (tid&1)
    const __nv_bfloat16 *ah_src, *al_src;
    {
        int row_g = block_row + (tid >> 1);
        size_t off;
        if (layer == 0) {
            int b = row_g >> 12, s = (row_g >> 10) & 3, n = row_g & 1023;
            if (iter > 0 && s == 0) {
                off = ((size_t)(b*NN + n))*HH;
                ah_src = g_lh + off; al_src = g_ll + off;
            } else {
                int t = left + s - (iter > 0 ? 1 : 0);
                off = ((size_t)((b*TT + t)*NN + n))*HH;
                ah_src = g_xh + off; al_src = g_xl + off;
            }
        } else {
            off = ((size_t)row_g)*HH;
            ah_src = g_h0h + off; al_src = g_h0l + off;
        }
        ah_src += (tid & 1)*8; al_src += (tid & 1)*8;
    }
    const __nv_bfloat16* bh_src = &g_wth[layer][(tid>>1)*HH + (tid&1)*8];
    const __nv_bfloat16* bl_src = &g_wtl[layer][(tid>>1)*HH + (tid&1)*8];
    int sa_off = (tid>>1)*AP + (tid&1)*8;
    int sb_off = (tid>>1)*BP + (tid&1)*8;

    float acc[16][4];
    #pragma unroll
    for (int nt = 0; nt < 16; nt++)
        #pragma unroll
        for (int j = 0; j < 4; j++) acc[nt][j] = 0.f;

    uint4 pah = *(const uint4*)ah_src;
    uint4 pal = *(const uint4*)al_src;
    uint4 pbh = *(const uint4*)bh_src;
    uint4 pbl = *(const uint4*)bl_src;

    int rq = warp*16 + (lane >> 2);
    int qo = (lane & 3) * 4;

    #pragma unroll
    for (int kc = 0; kc < 8; kc++) {
        int bi = kc & 1;
        *(uint4*)&sA[bi][0][sa_off] = pah;
        *(uint4*)&sA[bi][1][sa_off] = pal;
        *(uint4*)&sB[bi][0][sb_off] = pbh;
        *(uint4*)&sB[bi][1][sb_off] = pbl;
        __syncthreads();
        if (kc < 7) {
            pah = *(const uint4*)(ah_src + (kc+1)*16);
            pal = *(const uint4*)(al_src + (kc+1)*16);
            pbh = *(const uint4*)(bh_src + (kc+1)*16);
            pbl = *(const uint4*)(bl_src + (kc+1)*16);
        }
        // fragment loads: one 64-bit LDS each
        uint2 fah0 = *(const uint2*)&sA[bi][0][rq*AP + qo];        // {ah0, ah2}
        uint2 fah1 = *(const uint2*)&sA[bi][0][(rq+8)*AP + qo];    // {ah1, ah3}
        uint2 fal0 = *(const uint2*)&sA[bi][1][rq*AP + qo];
        uint2 fal1 = *(const uint2*)&sA[bi][1][(rq+8)*AP + qo];
        #pragma unroll
        for (int nt = 0; nt < 16; nt++) {
            int nb = nt*8 + (lane >> 2);
            uint2 fb_h = *(const uint2*)&sB[bi][0][nb*BP + qo];    // {bh0, bh1}
            uint2 fb_l = *(const uint2*)&sB[bi][1][nb*BP + qo];
            mma16816(acc[nt], fah0.x, fah1.x, fah0.y, fah1.y, fb_h.x, fb_h.y);
            mma16816(acc[nt], fah0.x, fah1.x, fah0.y, fah1.y, fb_l.x, fb_l.y);
            mma16816(acc[nt], fal0.x, fal1.x, fal0.y, fal1.y, fb_h.x, fb_h.y);
        }
        __syncthreads();
    }

    // epilogue: store C fp32 + fused el/er
    int r0 = block_row + warp*16 + (lane >> 2);
    int r8 = r0 + 8;
    float pl0[8], pl8[8], pr0[8], pr8[8];
    #pragma unroll
    for (int h = 0; h < 8; h++) { pl0[h]=0.f; pl8[h]=0.f; pr0[h]=0.f; pr8[h]=0.f; }
    #pragma unroll
    for (int nt = 0; nt < 16; nt++) {
        int c = nt*8 + (lane & 3)*2;
        int h = nt >> 1;
        float a0 = s_al[c], a1 = s_al[c+1];
        float b0 = s_ar[c], b1 = s_ar[c+1];
        pl0[h] += acc[nt][0]*a0 + acc[nt][1]*a1;
        pr0[h] += acc[nt][0]*b0 + acc[nt][1]*b1;
        pl8[h] += acc[nt][2]*a0 + acc[nt][3]*a1;
        pr8[h] += acc[nt][2]*b0 + acc[nt][3]*b1;
        float2 v0 = {acc[nt][0], acc[nt][1]};
        float2 v1 = {acc[nt][2], acc[nt][3]};
        *(float2*)&g_feat[(size_t)r0*HH + c] = v0;
        *(float2*)&g_feat[(size_t)r8*HH + c] = v1;
    }
    #pragma unroll
    for (int h = 0; h < 8; h++) {
        pl0[h] += __shfl_xor_sync(0xffffffffu, pl0[h], 1);
        pl0[h] += __shfl_xor_sync(0xffffffffu, pl0[h], 2);
        pl8[h] += __shfl_xor_sync(0xffffffffu, pl8[h], 1);
        pl8[h] += __shfl_xor_sync(0xffffffffu, pl8[h], 2);
        pr0[h] += __shfl_xor_sync(0xffffffffu, pr0[h], 1);
        pr0[h] += __shfl_xor_sync(0xffffffffu, pr0[h], 2);
        pr8[h] += __shfl_xor_sync(0xffffffffu, pr8[h], 1);
        pr8[h] += __shfl_xor_sync(0xffffffffu, pr8[h], 2);
    }
    if ((lane & 3) == 0) {
        #pragma unroll
        for (int h = 0; h < 8; h++) {
            g_el[(size_t)r0*8 + h] = pl0[h];
            g_el[(size_t)r8*8 + h] = pl8[h];
            g_er[(size_t)r0*8 + h] = pr0[h];
            g_er[(size_t)r8*8 + h] = pr8[h];
        }
    }
}

// ---------------- fused attention + aggregation (no shuffles) ------------------
__global__ __launch_bounds__(256) void k_attn_agg(int layer, const float* __restrict__ bias,
                                                  int iter, int left) {
    int warp = (blockIdx.x * blockDim.x + threadIdx.x) >> 5;
    int lane = threadIdx.x & 31;
    if (warp >= BB*NT) return;
    int v = warp & (NT-1);
    int b = warp >> 12;
    int o0 = g_off[v];
    int d = g_deg[v]; if (d > MAXDEG) d = MAXDEG;
    int head = lane >> 2;

    int sreg[MAXDEG];
    #pragma unroll
    for (int j = 0; j < MAXDEG; j++) {
        if (j < d) sreg[j] = g_srcs[o0 + j];     // warp-uniform broadcast load
    }

    size_t bNT = (size_t)b*NT;
    float erv = g_er[(bNT + v)*8 + head];
    float ereg[MAXDEG];
    float m = -1e30f;
    #pragma unroll
    for (int j = 0; j < MAXDEG; j++) {
        if (j < d) {
            float e = g_el[(bNT + sreg[j])*8 + head] + erv;
            e = e > 0.f ? e : LRELU_SLOPE*e;
            ereg[j] = e;
            m = fmaxf(m, e);
        }
    }
    float ssum = 0.f;
    #pragma unroll
    for (int j = 0; j < MAXDEG; j++) {
        if (j < d) { float w = __expf(ereg[j]-m); ereg[j] = w; ssum += w; }
    }
    float rinv = 1.0f/ssum;

    float4 acc = make_float4(0.f, 0.f, 0.f, 0.f);
    #pragma unroll
    for (int j = 0; j < MAXDEG; j++) {
        if (j < d) {
            float a = ereg[j];
            const float4 f = *(const float4*)&g_feat[(bNT + sreg[j])*128 + lane*4];
            acc.x += a*f.x; acc.y += a*f.y; acc.z += a*f.z; acc.w += a*f.w;
        }
    }
    acc.x *= rinv; acc.y *= rinv; acc.z *= rinv; acc.w *= rinv;
    float4 bv = *(const float4*)&bias[lane*4];
    acc.x += bv.x; acc.y += bv.y; acc.z += bv.z; acc.w += bv.w;
    size_t rbase = (size_t)warp*128;
    int c = lane*4;
    if (layer == 0) {
        acc.x = acc.x > 0.f ? acc.x : expm1f(acc.x);
        acc.y = acc.y > 0.f ? acc.y : expm1f(acc.y);
        acc.z = acc.z > 0.f ? acc.z : expm1f(acc.z);
        acc.w = acc.w > 0.f ? acc.w : expm1f(acc.w);
        // write k-permuted bf16 hi/lo (consumed only by layer-1 GEMM)
        __nv_bfloat16 h0 = __float2bfloat16_rn(acc.x);
        __nv_bfloat16 h1 = __float2bfloat16_rn(acc.y);
        __nv_bfloat16 h2 = __float2bfloat16_rn(acc.z);
        __nv_bfloat16 h3 = __float2bfloat16_rn(acc.w);
        int p0 = pos16(c), p1 = pos16(c+2);
        *(unsigned*)&g_h0h[rbase + p0] = packbf(acc.x, acc.y);
        *(unsigned*)&g_h0h[rbase + p1] = packbf(acc.z, acc.w);
        *(unsigned*)&g_h0l[rbase + p0] = packbf(acc.x - __bfloat162float(h0),
                                                acc.y - __bfloat162float(h1));
        *(unsigned*)&g_h0l[rbase + p1] = packbf(acc.z - __bfloat162float(h2),
                                                acc.w - __bfloat162float(h3));
    } else {
        const float4 rv = *(const float4*)(fs_row(warp, iter, left) + c);
        acc.x += rv.x; acc.y += rv.y; acc.z += rv.z; acc.w += rv.w;
        *(float4*)&g_h1[rbase + c] = acc;
    }
}

// ---------------- attention pooling (shuffle reductions) ----------------------
__global__ void k_pool(const float* __restrict__ q) {
    int bn = blockIdx.x;
    int b = bn >> 10;
    int n = bn & 1023;
    int tid = threadIdx.x;         // 128
    int lane = tid & 31, w = tid >> 5;
    __shared__ float sred[16];
    __shared__ float s2[8];
    float qv = q[n*128 + tid];
    float xs[4], p[4];
    #pragma unroll
    for (int t = 0; t < 4; t++) {
        xs[t] = g_h1[((size_t)b*NT + t*NN + n)*128 + tid];
        p[t] = xs[t]*qv;
    }
    #pragma unroll
    for (int t = 0; t < 4; t++) {
        #pragma unroll
        for (int o = 16; o > 0; o >>= 1) p[t] += __shfl_xor_sync(0xffffffffu, p[t], o);
    }
    if (lane == 0) {
        #pragma unroll
        for (int t = 0; t < 4; t++) sred[w*4+t] = p[t];
    }
    __syncthreads();
    float sc[4];
    #pragma unroll
    for (int t = 0; t < 4; t++) sc[t] = sred[t] + sred[4+t] + sred[8+t] + sred[12+t];
    float m = fmaxf(fmaxf(sc[0], sc[1]), fmaxf(sc[2], sc[3]));
    float e0 = __expf(sc[0]-m), e1 = __expf(sc[1]-m), e2 = __expf(sc[2]-m), e3 = __expf(sc[3]-m);
    float rs = 1.0f/(e0+e1+e2+e3);
    float lastv = (e0*xs[0] + e1*xs[1] + e2*xs[2] + e3*xs[3])*rs;
    g_last[(size_t)bn*128 + tid] = lastv;
    float s1v = lastv, s2v = lastv*lastv;
    #pragma unroll
    for (int o = 16; o > 0; o >>= 1) {
        s1v += __shfl_xor_sync(0xffffffffu, s1v, o);
        s2v += __shfl_xor_sync(0xffffffffu, s2v, o);
    }
    if (lane == 0) { s2[w] = s1v; s2[4+w] = s2v; }
    __syncthreads();
    if (tid == 0) atomicAdd(&g_stats[b*2],   s2[0]+s2[1]+s2[2]+s2[3]);
    if (tid == 1) atomicAdd(&g_stats[b*2+1], s2[4]+s2[5]+s2[6]+s2[7]);
}

// ---------------- per-batch layernorm: writes fp32 + permuted bf16 -------------
__global__ void k_norm() {
    int idx = blockIdx.x*blockDim.x + threadIdx.x;   // B*N*64 pairs
    int h = (idx & 63) * 2;
    size_t row = idx >> 6;
    int b = (int)(row >> 10);
    const float inv = 1.0f/(float)(NN*HH);
    float mu = g_stats[b*2]*inv;
    float var = g_stats[b*2+1]*inv - mu*mu;
    float rstd = rsqrtf(var + 1e-5f);
    float2 v = *(float2*)&g_last[row*HH + h];
    v.x = (v.x - mu)*rstd;
    v.y = (v.y - mu)*rstd;
    *(float2*)&g_last[row*HH + h] = v;
    __nv_bfloat16 h0 = __float2bfloat16_rn(v.x);
    __nv_bfloat16 h1 = __float2bfloat16_rn(v.y);
    int p = pos16(h);
    *(unsigned*)&g_lh[row*HH + p] = packbf(v.x, v.y);
    *(unsigned*)&g_ll[row*HH + p] = packbf(v.x - __bfloat162float(h0),
                                           v.y - __bfloat162float(h1));
}

// ---------------- output head (shuffle reductions) ----------------------------
__global__ void k_out(const float* __restrict__ w1, const float* __restrict__ b1,
                      const float* __restrict__ w2, const float* __restrict__ b2,
                      float* __restrict__ out) {
    int bn = blockIdx.x;
    int b = bn >> 10;
    int n = bn & 1023;
    int tid = threadIdx.x;         // 128
    int lane = tid & 31, w = tid >> 5;
    __shared__ float sred[4][12];
    float lv = g_last[(size_t)bn*128 + tid];
    float w2v = w2[tid];
    float p[12];
    #pragma unroll
    for (int s = 0; s < 12; s++) {
        float t = lv*w1[s] + b1[s];
        t = t > 0.f ? t : 0.f;
        p[s] = t*w2v;
    }
    #pragma unroll
    for (int s = 0; s < 12; s++) {
        #pragma unroll
        for (int o = 16; o > 0; o >>= 1) p[s] += __shfl_xor_sync(0xffffffffu, p[s], o);
    }
    if (lane == 0) {
        #pragma unroll
        for (int s = 0; s < 12; s++) sred[w][s] = p[s];
    }
    __syncthreads();
    if (tid < 12)
        out[((size_t)b*12 + tid)*NN + n] = sred[0][tid]+sred[1][tid]+sred[2][tid]+sred[3][tid] + b2[0];
}

// =============================================================================
extern "C" void kernel_launch(void* const* d_in, const int* in_sizes, int n_in,
                              void* d_out, int out_size) {
    const float* inputs   = (const float*)d_in[0];
    const float* W_in     = (const float*)d_in[1];
    const float* b_in     = (const float*)d_in[2];
    const float* spat     = (const float*)d_in[3];
    const float* temp     = (const float*)d_in[4];
    const float* gat_w0   = (const float*)d_in[5];
    const float* gat_al0  = (const float*)d_in[6];
    const float* gat_ar0  = (const float*)d_in[7];
    const float* gat_b0   = (const float*)d_in[8];
    const float* gat_w1   = (const float*)d_in[9];
    const float* gat_al1  = (const float*)d_in[10];
    const float* gat_ar1  = (const float*)d_in[11];
    const float* gat_b1   = (const float*)d_in[12];
    const float* agg_q    = (const float*)d_in[13];
    const float* w_out1   = (const float*)d_in[14];
    const float* b_out1   = (const float*)d_in[15];
    const float* w_out2   = (const float*)d_in[16];
    const float* b_out2   = (const float*)d_in[17];
    const int*   esrc     = (const int*)d_in[18];
    const int*   edst     = (const int*)d_in[19];
    int E = in_sizes[18];

    const int lefts[5] = {0, 4, 7, 10, 13};

    // index 3 (the ncu capture slot) is a GEMM
    k_wconv<<<128, 256>>>(gat_w0, gat_w1);                               // 0 (also zeros deg)
    k_x<<<(BB*TT*NN*64)/256, 256>>>(inputs, W_in, b_in, spat, temp);     // 1
    k_count<<<(E+255)/256, 256>>>(edst, E);                              // 2
    k_gemm<<<(BB*NT)/128, 256>>>(0, 0, 0, gat_al0, gat_ar0);             // 3 <- profiled
    k_scan<<<1, 1024>>>();                                               // 4
    k_fill<<<(E+255)/256, 256>>>(edst, E);                               // 5
    k_sort<<<(NT+127)/128, 128>>>(esrc);                                 // 6

    for (int it = 0; it < 5; it++) {
        if (it > 0)
            k_gemm<<<(BB*NT)/128, 256>>>(0, it, lefts[it], gat_al0, gat_ar0);
        k_attn_agg<<<(BB*NT)/8, 256>>>(0, gat_b0, it, lefts[it]);
        k_gemm<<<(BB*NT)/128, 256>>>(1, it, lefts[it], gat_al1, gat_ar1);
        k_attn_agg<<<(BB*NT)/8, 256>>>(1, gat_b1, it, lefts[it]);
        k_pool<<<BB*NN, 128>>>(agg_q);
        k_norm<<<(BB*NN*64)/256, 256>>>();
    }

    k_out<<<BB*NN, 128>>>(w_out1, b_out1, w_out2, b_out2, (float*)d_out);
}

// round 5
// speedup vs baseline: 1.3943x; 1.3943x over previous
#include <cuda_runtime.h>
#include <cuda_bf16.h>
#include <cstdint>

#define BB 8
#define TT 16
#define NN 1024
#define HH 128
#define NHEADS 8
#define SNP 4
#define NT 4096
#define EMAX 65536
#define LRELU_SLOPE 0.2f
#define MAXDEG 16
#define AP 24
#define BP 16

// ---------------- scratch (device globals) ------------------------------------
__device__ __nv_bfloat16 g_xh[BB*TT*NN*HH];   // k-permuted bf16 hi of x
__device__ __nv_bfloat16 g_xl[BB*TT*NN*HH];   // k-permuted bf16 lo of x
__device__ float g_feat[BB*NT*HH];
__device__ __nv_bfloat16 g_h0h[BB*NT*HH];     // layer0 out, k-permuted bf16
__device__ __nv_bfloat16 g_h0l[BB*NT*HH];
__device__ float g_el[BB*NT*NHEADS];
__device__ float g_er[BB*NT*NHEADS];
__device__ float g_last[BB*NN*HH];            // RAW pooled values (pre-norm)
__device__ __nv_bfloat16 g_lh[BB*NN*HH];      // raw pooled, k-permuted bf16 hi
__device__ __nv_bfloat16 g_ll[BB*NN*HH];      // raw pooled, k-permuted bf16 lo
__device__ float g_stats[2][2*BB];            // ping-pong per-batch sum,sumsq
__device__ float g_wsum[2][HH];               // colsum of W per layer
__device__ int   g_deg[NT];                   // zeroed by k_out tail of prev call
__device__ int   g_cnt[NT];
__device__ int   g_off[NT+1];
__device__ int   g_eid[EMAX];
__device__ int   g_srcs[EMAX];
__device__ __nv_bfloat16 g_wth[2][HH*HH];     // W^T, k-permuted
__device__ __nv_bfloat16 g_wtl[2][HH*HH];

// ---------------- helpers ------------------------------------------------------
__device__ __forceinline__ int pos16(int k) {
    return (k & ~15) | (((k>>1)&3)<<2) | (((k>>3)&1)<<1) | (k&1);
}
__device__ __forceinline__ unsigned packbf(float x, float y) {
    __nv_bfloat162 t = __floats2bfloat162_rn(x, y);
    return *(unsigned*)&t;
}
__device__ __forceinline__ float2 bf2f2(unsigned u) {
    __nv_bfloat162 t = *(__nv_bfloat162*)&u;
    return make_float2(__bfloat162float(t.x), __bfloat162float(t.y));
}
__device__ __forceinline__ void mma16816(float* c, unsigned a0, unsigned a1,
                                         unsigned a2, unsigned a3,
                                         unsigned b0, unsigned b1) {
    asm volatile(
        "mma.sync.aligned.m16n8k16.row.col.f32.bf16.bf16.f32 "
        "{%0,%1,%2,%3},{%4,%5,%6,%7},{%8,%9},{%0,%1,%2,%3};\n"
        : "+f"(c[0]), "+f"(c[1]), "+f"(c[2]), "+f"(c[3])
        : "r"(a0), "r"(a1), "r"(a2), "r"(a3), "r"(b0), "r"(b1));
}

// ---------------- prolog: x + wconv + CSR-count + wsum (one kernel) -----------
__global__ __launch_bounds__(256) void k_prolog(
        const float* __restrict__ in, const float* __restrict__ Win,
        const float* __restrict__ bin, const float* __restrict__ spat,
        const float* __restrict__ temp, const float* __restrict__ W0,
        const float* __restrict__ W1, const int* __restrict__ edst, int E) {
    int blk = blockIdx.x;
    if (blk < 32768) {
        // ---- x precompute (pair per thread), bf16 hi/lo only ----
        int idx = blk*256 + threadIdx.x;          // B*T*N*64
        int h = (idx & 63) * 2;
        int n = (idx >> 6) & 1023;
        int t = (idx >> 16) & 15;
        int b = idx >> 20;
        size_t ib = ((size_t)(b*TT + t)*NN + n)*2;
        float i0 = in[ib], i1 = in[ib+1];
        float tv = temp[n*16+t];
        float v0 = i0*Win[h]   + i1*Win[128+h]   + bin[h]   + spat[n*128+h]   + tv;
        float v1 = i0*Win[h+1] + i1*Win[128+h+1] + bin[h+1] + spat[n*128+h+1] + tv;
        size_t row = ((size_t)(b*TT + t)*NN + n)*HH;
        __nv_bfloat16 h0 = __float2bfloat16_rn(v0);
        __nv_bfloat16 h1 = __float2bfloat16_rn(v1);
        int p = pos16(h);
        *(unsigned*)&g_xh[row + p] = packbf(v0, v1);
        *(unsigned*)&g_xl[row + p] = packbf(v0 - __bfloat162float(h0),
                                            v1 - __bfloat162float(h1));
    } else if (blk < 32896) {
        // ---- weight conversion ----
        int id = (blk - 32768)*256 + threadIdx.x;  // 0..32767
        int layer = id >> 14;
        int r = id & 16383;
        int k = r >> 7, n = r & 127;
        float w = (layer ? W1 : W0)[k*HH + n];
        __nv_bfloat16 hi = __float2bfloat16_rn(w);
        __nv_bfloat16 lo = __float2bfloat16_rn(w - __bfloat162float(hi));
        g_wth[layer][n*HH + pos16(k)] = hi;
        g_wtl[layer][n*HH + pos16(k)] = lo;
    } else if (blk < 33052) {
        // ---- CSR degree count (g_deg pre-zeroed by prev call's k_out) ----
        int i = (blk - 32896)*256 + threadIdx.x;
        if (i < E) atomicAdd(&g_deg[edst[i]], 1);
    } else {
        // ---- wsum: colsum of W per layer ----
        int id = threadIdx.x;                      // 256
        int layer = id >> 7, n = id & 127;
        const float* W = layer ? W1 : W0;
        float s = 0.f;
        for (int k = 0; k < HH; k++) s += W[k*HH + n];
        g_wsum[layer][n] = s;
    }
}

// ---------------- CSR build ---------------------------------------------------
__global__ void k_scan() {
    __shared__ int sh[1024];
    int tid = threadIdx.x;
    int d0 = g_deg[tid*4+0], d1 = g_deg[tid*4+1], d2 = g_deg[tid*4+2], d3 = g_deg[tid*4+3];
    int tot = d0+d1+d2+d3;
    sh[tid] = tot; __syncthreads();
    for (int o = 1; o < 1024; o <<= 1) {
        int v = (tid >= o) ? sh[tid-o] : 0;
        __syncthreads();
        sh[tid] += v;
        __syncthreads();
    }
    int excl = sh[tid] - tot;
    g_off[tid*4+0] = excl;
    g_off[tid*4+1] = excl + d0;
    g_off[tid*4+2] = excl + d0 + d1;
    g_off[tid*4+3] = excl + d0 + d1 + d2;
    if (tid == 1023) g_off[NT] = sh[1023];
}
__global__ void k_fill(const int* __restrict__ edst, int E) {
    int i = blockIdx.x*blockDim.x + threadIdx.x;
    if (i >= E) return;
    int v = edst[i];
    int slot = g_off[v] + atomicAdd(&g_cnt[v], 1);
    g_eid[slot] = i;
}
__global__ void k_sort(const int* __restrict__ esrc) {
    int v = blockIdx.x*blockDim.x + threadIdx.x;
    if (v >= NT) return;
    int o0 = g_off[v];
    int d = g_deg[v]; if (d > MAXDEG) d = MAXDEG;
    for (int i = 1; i < d; i++) {
        int key = g_eid[o0+i];
        int j = i-1;
        while (j >= 0 && g_eid[o0+j] > key) { g_eid[o0+j+1] = g_eid[o0+j]; j--; }
        g_eid[o0+j+1] = key;
    }
    for (int j = 0; j < d; j++) g_srcs[o0+j] = esrc[g_eid[o0+j]];
}

// ---------------- MMA GEMM (bf16 split, double-buffered, fused el/er) ---------
// Layer0 with iter>0, s==0 blocks get the layernorm affine correction:
//   feat_norm = rstd*feat_raw - mu*rstd*wsum[n]
__global__ __launch_bounds__(256, 2) void k_gemm(int layer, int iter, int left,
                                                 const float* __restrict__ al,
                                                 const float* __restrict__ ar) {
    __shared__ __nv_bfloat16 sA[2][2][128*AP];
    __shared__ __nv_bfloat16 sB[2][2][128*BP];
    __shared__ float s_al[128], s_ar[128], s_w[128];
    int tid = threadIdx.x;
    int lane = tid & 31, warp = tid >> 5;
    int block_row = blockIdx.x * 128;

    if (layer == 0 && blockIdx.x == 0 && tid < 2*BB) g_stats[iter&1][tid] = 0.f;
    if (tid < 128) { s_al[tid] = al[tid]; s_ar[tid] = ar[tid]; s_w[tid] = g_wsum[layer][tid]; }

    // staging source: thread stages 8 elems of row (tid>>1), half (tid&1)
    const __nv_bfloat16 *ah_src, *al_src;
    {
        int row_g = block_row + (tid >> 1);
        size_t off;
        if (layer == 0) {
            int b = row_g >> 12, s = (row_g >> 10) & 3, n = row_g & 1023;
            if (iter > 0 && s == 0) {
                off = ((size_t)(b*NN + n))*HH;
                ah_src = g_lh + off; al_src = g_ll + off;
            } else {
                int t = left + s - (iter > 0 ? 1 : 0);
                off = ((size_t)((b*TT + t)*NN + n))*HH;
                ah_src = g_xh + off; al_src = g_xl + off;
            }
        } else {
            off = ((size_t)row_g)*HH;
            ah_src = g_h0h + off; al_src = g_h0l + off;
        }
        ah_src += (tid & 1)*8; al_src += (tid & 1)*8;
    }
    const __nv_bfloat16* bh_src = &g_wth[layer][(tid>>1)*HH + (tid&1)*8];
    const __nv_bfloat16* bl_src = &g_wtl[layer][(tid>>1)*HH + (tid&1)*8];
    int sa_off = (tid>>1)*AP + (tid&1)*8;
    int sb_off = (tid>>1)*BP + (tid&1)*8;

    float acc[16][4];
    #pragma unroll
    for (int nt = 0; nt < 16; nt++)
        #pragma unroll
        for (int j = 0; j < 4; j++) acc[nt][j] = 0.f;

    uint4 pah = *(const uint4*)ah_src;
    uint4 pal = *(const uint4*)al_src;
    uint4 pbh = *(const uint4*)bh_src;
    uint4 pbl = *(const uint4*)bl_src;

    int rq = warp*16 + (lane >> 2);
    int qo = (lane & 3) * 4;

    #pragma unroll
    for (int kc = 0; kc < 8; kc++) {
        int bi = kc & 1;
        *(uint4*)&sA[bi][0][sa_off] = pah;
        *(uint4*)&sA[bi][1][sa_off] = pal;
        *(uint4*)&sB[bi][0][sb_off] = pbh;
        *(uint4*)&sB[bi][1][sb_off] = pbl;
        __syncthreads();
        if (kc < 7) {
            pah = *(const uint4*)(ah_src + (kc+1)*16);
            pal = *(const uint4*)(al_src + (kc+1)*16);
            pbh = *(const uint4*)(bh_src + (kc+1)*16);
            pbl = *(const uint4*)(bl_src + (kc+1)*16);
        }
        uint2 fah0 = *(const uint2*)&sA[bi][0][rq*AP + qo];
        uint2 fah1 = *(const uint2*)&sA[bi][0][(rq+8)*AP + qo];
        uint2 fal0 = *(const uint2*)&sA[bi][1][rq*AP + qo];
        uint2 fal1 = *(const uint2*)&sA[bi][1][(rq+8)*AP + qo];
        #pragma unroll
        for (int nt = 0; nt < 16; nt++) {
            int nb = nt*8 + (lane >> 2);
            uint2 fb_h = *(const uint2*)&sB[bi][0][nb*BP + qo];
            uint2 fb_l = *(const uint2*)&sB[bi][1][nb*BP + qo];
            mma16816(acc[nt], fah0.x, fah1.x, fah0.y, fah1.y, fb_h.x, fb_h.y);
            mma16816(acc[nt], fah0.x, fah1.x, fah0.y, fah1.y, fb_l.x, fb_l.y);
            mma16816(acc[nt], fal0.x, fal1.x, fal0.y, fal1.y, fb_h.x, fb_h.y);
        }
        __syncthreads();
    }

    // layernorm affine correction (per-block uniform)
    float cs = 1.f, csh = 0.f;
    if (layer == 0 && iter > 0 && ((block_row >> 10) & 3) == 0) {
        int b = block_row >> 12;
        const float inv = 1.0f/(float)(NN*HH);
        float s1 = g_stats[(iter-1)&1][b*2];
        float s2 = g_stats[(iter-1)&1][b*2+1];
        float mu = s1*inv;
        float var = s2*inv - mu*mu;
        float rstd = rsqrtf(var + 1e-5f);
        cs = rstd; csh = -mu*rstd;
    }

    // epilogue: correct, store C fp32, fused el/er
    int r0 = block_row + warp*16 + (lane >> 2);
    int r8 = r0 + 8;
    float pl0[8], pl8[8], pr0[8], pr8[8];
    #pragma unroll
    for (int h = 0; h < 8; h++) { pl0[h]=0.f; pl8[h]=0.f; pr0[h]=0.f; pr8[h]=0.f; }
    #pragma unroll
    for (int nt = 0; nt < 16; nt++) {
        int c = nt*8 + (lane & 3)*2;
        int h = nt >> 1;
        acc[nt][0] = acc[nt][0]*cs + csh*s_w[c];
        acc[nt][1] = acc[nt][1]*cs + csh*s_w[c+1];
        acc[nt][2] = acc[nt][2]*cs + csh*s_w[c];
        acc[nt][3] = acc[nt][3]*cs + csh*s_w[c+1];
        float a0 = s_al[c], a1 = s_al[c+1];
        float b0 = s_ar[c], b1 = s_ar[c+1];
        pl0[h] += acc[nt][0]*a0 + acc[nt][1]*a1;
        pr0[h] += acc[nt][0]*b0 + acc[nt][1]*b1;
        pl8[h] += acc[nt][2]*a0 + acc[nt][3]*a1;
        pr8[h] += acc[nt][2]*b0 + acc[nt][3]*b1;
        float2 v0 = {acc[nt][0], acc[nt][1]};
        float2 v1 = {acc[nt][2], acc[nt][3]};
        *(float2*)&g_feat[(size_t)r0*HH + c] = v0;
        *(float2*)&g_feat[(size_t)r8*HH + c] = v1;
    }
    #pragma unroll
    for (int h = 0; h < 8; h++) {
        pl0[h] += __shfl_xor_sync(0xffffffffu, pl0[h], 1);
        pl0[h] += __shfl_xor_sync(0xffffffffu, pl0[h], 2);
        pl8[h] += __shfl_xor_sync(0xffffffffu, pl8[h], 1);
        pl8[h] += __shfl_xor_sync(0xffffffffu, pl8[h], 2);
        pr0[h] += __shfl_xor_sync(0xffffffffu, pr0[h], 1);
        pr0[h] += __shfl_xor_sync(0xffffffffu, pr0[h], 2);
        pr8[h] += __shfl_xor_sync(0xffffffffu, pr8[h], 1);
        pr8[h] += __shfl_xor_sync(0xffffffffu, pr8[h], 2);
    }
    if ((lane & 3) == 0) {
        #pragma unroll
        for (int h = 0; h < 8; h++) {
            g_el[(size_t)r0*8 + h] = pl0[h];
            g_el[(size_t)r8*8 + h] = pl8[h];
            g_er[(size_t)r0*8 + h] = pr0[h];
            g_er[(size_t)r8*8 + h] = pr8[h];
        }
    }
}

// ---------------- GAT gather (shared by agg kernels) --------------------------
__device__ __forceinline__ float4 gat_gather(int v, size_t bNT, int lane) {
    int o0 = g_off[v];
    int d = g_deg[v]; if (d > MAXDEG) d = MAXDEG;
    int head = lane >> 2;

    int sreg[MAXDEG];
    #pragma unroll
    for (int j = 0; j < MAXDEG; j++)
        if (j < d) sreg[j] = g_srcs[o0 + j];

    float erv = g_er[(bNT + v)*8 + head];
    float ereg[MAXDEG];
    float m = -1e30f;
    #pragma unroll
    for (int j = 0; j < MAXDEG; j++) {
        if (j < d) {
            float e = g_el[(bNT + sreg[j])*8 + head] + erv;
            e = e > 0.f ? e : LRELU_SLOPE*e;
            ereg[j] = e;
            m = fmaxf(m, e);
        }
    }
    float ssum = 0.f;
    #pragma unroll
    for (int j = 0; j < MAXDEG; j++)
        if (j < d) { float w = __expf(ereg[j]-m); ereg[j] = w; ssum += w; }
    float rinv = 1.0f/ssum;

    float4 acc = make_float4(0.f, 0.f, 0.f, 0.f);
    #pragma unroll
    for (int j = 0; j < MAXDEG; j++) {
        if (j < d) {
            float a = ereg[j];
            const float4 f = *(const float4*)&g_feat[(bNT + sreg[j])*128 + lane*4];
            acc.x += a*f.x; acc.y += a*f.y; acc.z += a*f.z; acc.w += a*f.w;
        }
    }
    acc.x *= rinv; acc.y *= rinv; acc.z *= rinv; acc.w *= rinv;
    return acc;
}

// ---------------- layer-0 aggregation (ELU, writes bf16 split) -----------------
__global__ __launch_bounds__(256) void k_agg0(const float* __restrict__ bias) {
    int warp = (blockIdx.x * blockDim.x + threadIdx.x) >> 5;
    int lane = threadIdx.x & 31;
    int v = warp & (NT-1);
    int b = warp >> 12;
    size_t bNT = (size_t)b*NT;
    float4 acc = gat_gather(v, bNT, lane);
    float4 bv = *(const float4*)&bias[lane*4];
    acc.x += bv.x; acc.y += bv.y; acc.z += bv.z; acc.w += bv.w;
    acc.x = acc.x > 0.f ? acc.x : expm1f(acc.x);
    acc.y = acc.y > 0.f ? acc.y : expm1f(acc.y);
    acc.z = acc.z > 0.f ? acc.z : expm1f(acc.z);
    acc.w = acc.w > 0.f ? acc.w : expm1f(acc.w);
    size_t rbase = (size_t)warp*128;
    int c = lane*4;
    __nv_bfloat16 h0 = __float2bfloat16_rn(acc.x);
    __nv_bfloat16 h1 = __float2bfloat16_rn(acc.y);
    __nv_bfloat16 h2 = __float2bfloat16_rn(acc.z);
    __nv_bfloat16 h3 = __float2bfloat16_rn(acc.w);
    int p0 = pos16(c), p1 = pos16(c+2);
    *(unsigned*)&g_h0h[rbase + p0] = packbf(acc.x, acc.y);
    *(unsigned*)&g_h0h[rbase + p1] = packbf(acc.z, acc.w);
    *(unsigned*)&g_h0l[rbase + p0] = packbf(acc.x - __bfloat162float(h0),
                                            acc.y - __bfloat162float(h1));
    *(unsigned*)&g_h0l[rbase + p1] = packbf(acc.z - __bfloat162float(h2),
                                            acc.w - __bfloat162float(h3));
}

// ---------------- fused layer-1 aggregation + residual + pooling --------------
// block = 2 nodes x 4 snapshots (8 warps). h1 never hits gmem.
__global__ __launch_bounds__(256) void k_agg1pool(const float* __restrict__ bias,
                                                  const float* __restrict__ q,
                                                  int iter, int left) {
    __shared__ float ssc[8];
    __shared__ float sbuf[8][128];
    __shared__ float sst[16];
    int tid = threadIdx.x, lane = tid & 31, w = tid >> 5;
    int b = blockIdx.x >> 9;
    int n0 = (blockIdx.x & 511) * 2;
    int node = n0 + (w >> 2);
    int s = w & 3;
    int v = s*NN + node;
    size_t bNT = (size_t)b*NT;

    // --- layer-1 GAT row ---
    float4 acc = gat_gather(v, bNT, lane);
    float4 bv = *(const float4*)&bias[lane*4];
    acc.x += bv.x; acc.y += bv.y; acc.z += bv.z; acc.w += bv.w;

    // --- residual ---
    float4 rv;
    size_t lrow = ((size_t)(b*NN + node))*HH;
    if (iter > 0 && s == 0) {
        const float inv = 1.0f/(float)(NN*HH);
        float s1 = g_stats[(iter-1)&1][b*2];
        float s2 = g_stats[(iter-1)&1][b*2+1];
        float mu = s1*inv;
        float var = s2*inv - mu*mu;
        float rstd = rsqrtf(var + 1e-5f);
        float4 lv = *(const float4*)&g_last[lrow + lane*4];
        rv.x = (lv.x-mu)*rstd; rv.y = (lv.y-mu)*rstd;
        rv.z = (lv.z-mu)*rstd; rv.w = (lv.w-mu)*rstd;
    } else {
        int t = left + s - (iter > 0 ? 1 : 0);
        size_t xrow = ((size_t)((b*TT + t)*NN + node))*HH;
        int c = lane*4;
        int p0 = pos16(c), p1 = pos16(c+2);
        float2 a0 = bf2f2(*(unsigned*)&g_xh[xrow+p0]);
        float2 a1 = bf2f2(*(unsigned*)&g_xh[xrow+p1]);
        float2 l0 = bf2f2(*(unsigned*)&g_xl[xrow+p0]);
        float2 l1 = bf2f2(*(unsigned*)&g_xl[xrow+p1]);
        rv = make_float4(a0.x+l0.x, a0.y+l0.y, a1.x+l1.x, a1.y+l1.y);
    }
    acc.x += rv.x; acc.y += rv.y; acc.z += rv.z; acc.w += rv.w;

    // --- score: dot(h1row, q[node]) ---
    float4 qv = *(const float4*)&q[node*HH + lane*4];
    float sc = acc.x*qv.x + acc.y*qv.y + acc.z*qv.z + acc.w*qv.w;
    #pragma unroll
    for (int o = 16; o > 0; o >>= 1) sc += __shfl_xor_sync(0xffffffffu, sc, o);
    if (lane == 0) ssc[w] = sc;
    __syncthreads();

    // --- softmax over 4 snapshots, weighted write to smem ---
    int base = (w >> 2) * 4;
    float c0 = ssc[base], c1 = ssc[base+1], c2 = ssc[base+2], c3 = ssc[base+3];
    float m = fmaxf(fmaxf(c0, c1), fmaxf(c2, c3));
    float e0 = __expf(c0-m), e1 = __expf(c1-m), e2 = __expf(c2-m), e3 = __expf(c3-m);
    float alpha = __expf(ssc[base+s]-m) / (e0+e1+e2+e3);
    *(float4*)&sbuf[w][lane*4] = make_float4(acc.x*alpha, acc.y*alpha,
                                             acc.z*alpha, acc.w*alpha);
    __syncthreads();

    // --- final pooled row: 256 threads -> 2 nodes x 128 cols ---
    int ns = tid >> 7, c = tid & 127;
    int wb = ns*4;
    float lastv = sbuf[wb][c] + sbuf[wb+1][c] + sbuf[wb+2][c] + sbuf[wb+3][c];
    size_t lr = ((size_t)(b*NN + n0 + ns))*HH;
    g_last[lr + c] = lastv;
    __nv_bfloat16 hi = __float2bfloat16_rn(lastv);
    int p = pos16(c);
    g_lh[lr + p] = hi;
    g_ll[lr + p] = __float2bfloat16_rn(lastv - __bfloat162float(hi));

    // --- per-batch stats (raw values) ---
    float s1v = lastv, s2v = lastv*lastv;
    #pragma unroll
    for (int o = 16; o > 0; o >>= 1) {
        s1v += __shfl_xor_sync(0xffffffffu, s1v, o);
        s2v += __shfl_xor_sync(0xffffffffu, s2v, o);
    }
    if (lane == 0) { sst[w] = s1v; sst[8+w] = s2v; }
    __syncthreads();
    if (tid == 0)
        atomicAdd(&g_stats[iter&1][b*2],
                  sst[0]+sst[1]+sst[2]+sst[3]+sst[4]+sst[5]+sst[6]+sst[7]);
    if (tid == 1)
        atomicAdd(&g_stats[iter&1][b*2+1],
                  sst[8]+sst[9]+sst[10]+sst[11]+sst[12]+sst[13]+sst[14]+sst[15]);
}

// ---------------- output head (+ zero deg/cnt for next call) -------------------
__global__ void k_out(const float* __restrict__ w1, const float* __restrict__ b1,
                      const float* __restrict__ w2, const float* __restrict__ b2,
                      float* __restrict__ out) {
    int bn = blockIdx.x;
    int tid = threadIdx.x;         // 128
    if (bn < 32)            { int z = bn*128 + tid;      g_deg[z] = 0; }
    else if (bn < 64)       { int z = (bn-32)*128 + tid; g_cnt[z] = 0; }
    int b = bn >> 10;
    int n = bn & 1023;
    int lane = tid & 31, w = tid >> 5;
    __shared__ float sred[4][12];
    const float inv = 1.0f/(float)(NN*HH);
    float s1 = g_stats[0][b*2];       // iter 4 -> buffer 0
    float s2 = g_stats[0][b*2+1];
    float mu = s1*inv;
    float var = s2*inv - mu*mu;
    float rstd = rsqrtf(var + 1e-5f);
    float lv = (g_last[(size_t)bn*128 + tid] - mu)*rstd;
    float w2v = w2[tid];
    float p[12];
    #pragma unroll
    for (int s = 0; s < 12; s++) {
        float t = lv*w1[s] + b1[s];
        t = t > 0.f ? t : 0.f;
        p[s] = t*w2v;
    }
    #pragma unroll
    for (int s = 0; s < 12; s++) {
        #pragma unroll
        for (int o = 16; o > 0; o >>= 1) p[s] += __shfl_xor_sync(0xffffffffu, p[s], o);
    }
    if (lane == 0) {
        #pragma unroll
        for (int s = 0; s < 12; s++) sred[w][s] = p[s];
    }
    __syncthreads();
    if (tid < 12)
        out[((size_t)b*12 + tid)*NN + n] = sred[0][tid]+sred[1][tid]+sred[2][tid]+sred[3][tid] + b2[0];
}

// =============================================================================
extern "C" void kernel_launch(void* const* d_in, const int* in_sizes, int n_in,
                              void* d_out, int out_size) {
    const float* inputs   = (const float*)d_in[0];
    const float* W_in     = (const float*)d_in[1];
    const float* b_in     = (const float*)d_in[2];
    const float* spat     = (const float*)d_in[3];
    const float* temp     = (const float*)d_in[4];
    const float* gat_w0   = (const float*)d_in[5];
    const float* gat_al0  = (const float*)d_in[6];
    const float* gat_ar0  = (const float*)d_in[7];
    const float* gat_b0   = (const float*)d_in[8];
    const float* gat_w1   = (const float*)d_in[9];
    const float* gat_al1  = (const float*)d_in[10];
    const float* gat_ar1  = (const float*)d_in[11];
    const float* gat_b1   = (const float*)d_in[12];
    const float* agg_q    = (const float*)d_in[13];
    const float* w_out1   = (const float*)d_in[14];
    const float* b_out1   = (const float*)d_in[15];
    const float* w_out2   = (const float*)d_in[16];
    const float* b_out2   = (const float*)d_in[17];
    const int*   esrc     = (const int*)d_in[18];
    const int*   edst     = (const int*)d_in[19];
    int E = in_sizes[18];

    const int lefts[5] = {0, 4, 7, 10, 13};

    k_prolog<<<33053, 256>>>(inputs, W_in, b_in, spat, temp,
                             gat_w0, gat_w1, edst, E);                   // 0
    k_scan<<<1, 1024>>>();                                               // 1
    k_fill<<<(E+255)/256, 256>>>(edst, E);                               // 2
    k_gemm<<<(BB*NT)/128, 256>>>(0, 0, 0, gat_al0, gat_ar0);             // 3 <- profiled
    k_sort<<<(NT+127)/128, 128>>>(esrc);                                 // 4

    for (int it = 0; it < 5; it++) {
        if (it > 0)
            k_gemm<<<(BB*NT)/128, 256>>>(0, it, lefts[it], gat_al0, gat_ar0);
        k_agg0<<<(BB*NT)/8, 256>>>(gat_b0);
        k_gemm<<<(BB*NT)/128, 256>>>(1, it, lefts[it], gat_al1, gat_ar1);
        k_agg1pool<<<(BB*NN)/2, 256>>>(gat_b1, agg_q, it, lefts[it]);
    }

    k_out<<<BB*NN, 128>>>(w_out1, b_out1, w_out2, b_out2, (float*)d_out);
}